// round 12
// baseline (speedup 1.0000x reference)
#include <cuda_runtime.h>
#include <cuda_fp16.h>
#include <math.h>
#include <stdint.h>

// ---------------- problem constants ----------------
#define BB      16
#define W_RES   64
#define CC      512
#define NHEAD   16
#define NWTOK   64
#define HD      32
#define HID     2048
#define NWIN    1024
#define MTOT    65536
#define PLANE   33554432ull // MTOT * CC elements per q/k/v plane

#define PI_F    3.14159265358979323846f

// ---------------- scratch ----------------
__device__ float g_xnw[(size_t)MTOT * CC];      // as __half (LN1 out)
__device__ float g_qkv[3ull * MTOT * CC];       // as __half q/k/v planes
__device__ float g_attnout[(size_t)MTOT * CC];  // as __half
__device__ float g_x2[(size_t)MTOT * CC];       // fp32 (residual)
__device__ float g_xm[(size_t)MTOT * CC];       // as __half (LN2 out)
__device__ float g_hbuf[(size_t)MTOT * HID];    // as __half (gelu out)
__device__ float g_aphi[NHEAD * NWTOK * NWTOK];
__device__ __half g_wh[3145728];                // fp16 weights: qkv|proj|fc1|fc2

#define WH_QKV  0
#define WH_PROJ 786432
#define WH_FC1  1048576
#define WH_FC2  2097152

__device__ __forceinline__ size_t win_to_nat(int m) {
    int w = m >> 6, n = m & 63;
    int b = w >> 6, wy = (w >> 3) & 7, wx = w & 7;
    int ny = n >> 3, nx = n & 7;
    return (size_t)b * 4096 + (size_t)(wy * 8 + ny) * 64 + (wx * 8 + nx);
}

// ---------------- PTX helpers ----------------
__device__ __forceinline__ uint32_t smem_u32(const void* p) {
    uint32_t a;
    asm("{ .reg .u64 tmp; cvta.to.shared.u64 tmp, %1; cvt.u32.u64 %0, tmp; }"
        : "=r"(a) : "l"(p));
    return a;
}
__device__ __forceinline__ void cp16(uint32_t smem, const void* g) {
    asm volatile("cp.async.cg.shared.global [%0], [%1], 16;\n" :: "r"(smem), "l"(g));
}
__device__ __forceinline__ void cp_commit() {
    asm volatile("cp.async.commit_group;\n" ::: "memory");
}
template <int N>
__device__ __forceinline__ void cp_wait() {
    asm volatile("cp.async.wait_group %0;\n" :: "n"(N) : "memory");
}
__device__ __forceinline__ void ldsm_x4(uint32_t* r, uint32_t addr) {
    asm volatile("ldmatrix.sync.aligned.m8n8.x4.shared.b16 {%0,%1,%2,%3}, [%4];"
                 : "=r"(r[0]), "=r"(r[1]), "=r"(r[2]), "=r"(r[3]) : "r"(addr));
}
__device__ __forceinline__ void ldsm_x2(uint32_t* r, uint32_t addr) {
    asm volatile("ldmatrix.sync.aligned.m8n8.x2.shared.b16 {%0,%1}, [%2];"
                 : "=r"(r[0]), "=r"(r[1]) : "r"(addr));
}
__device__ __forceinline__ void ldsm_x2_trans(uint32_t* r, uint32_t addr) {
    asm volatile("ldmatrix.sync.aligned.m8n8.x2.trans.shared.b16 {%0,%1}, [%2];"
                 : "=r"(r[0]), "=r"(r[1]) : "r"(addr));
}
__device__ __forceinline__ void mma_f16(float* c, const uint32_t* a, const uint32_t* b) {
    asm volatile(
        "mma.sync.aligned.m16n8k16.row.col.f32.f16.f16.f32 "
        "{%0,%1,%2,%3}, {%4,%5,%6,%7}, {%8,%9}, {%0,%1,%2,%3};\n"
        : "+f"(c[0]), "+f"(c[1]), "+f"(c[2]), "+f"(c[3])
        : "r"(a[0]), "r"(a[1]), "r"(a[2]), "r"(a[3]), "r"(b[0]), "r"(b[1]));
}
__device__ __forceinline__ uint32_t pack2(float a, float b) {
    __half2 h = __floats2half2_rn(a, b);
    return *reinterpret_cast<uint32_t*>(&h);
}

// ---------------- weight fp32 -> fp16 (vectorized) ----------------
__global__ void w2h_kernel(const float* __restrict__ w, __half* __restrict__ o, int n4) {
    int i = blockIdx.x * blockDim.x + threadIdx.x;
    if (i < n4) {
        float4 v = ((const float4*)w)[i];
        __half2 a = __floats2half2_rn(v.x, v.y);
        __half2 b = __floats2half2_rn(v.z, v.w);
        uint2 pk = make_uint2(*(uint32_t*)&a, *(uint32_t*)&b);
        ((uint2*)o)[i] = pk;
    }
}

// ---------------- A_phi precompute ----------------
__global__ void aphi_kernel(const float* __restrict__ a_p,
                            const float* __restrict__ b_p,
                            float* __restrict__ aphi) {
    int i = blockIdx.x, j = threadIdx.x;
    int az = (i & 7) - (j & 7);
    int ip = (az + 15) % 15;
    float azf = (float)az * (2.0f * PI_F / (float)W_RES);
    float c = cosf(azf), s = sinf(azf);
#pragma unroll
    for (int h = 0; h < NHEAD; h++)
        aphi[((h * 64 + i) << 6) + j] = a_p[ip * NHEAD + h] * c + b_p[ip * NHEAD + h] * s;
}

// ---------------- LayerNorm (fp32 in, fp16 out) ----------------
template <int WINDOWED>
__global__ __launch_bounds__(128) void ln_kernel(const float* __restrict__ x,
                                                 const float* __restrict__ gamma,
                                                 const float* __restrict__ beta,
                                                 __half* __restrict__ out) {
    int m = blockIdx.x;
    size_t src = WINDOWED ? win_to_nat(m) : (size_t)m;
    int t = threadIdx.x;

    const float4 v = *(const float4*)(x + src * CC + t * 4);
    float s  = v.x + v.y + v.z + v.w;
    float s2 = v.x * v.x + v.y * v.y + v.z * v.z + v.w * v.w;
#pragma unroll
    for (int o = 16; o > 0; o >>= 1) {
        s  += __shfl_down_sync(0xffffffffu, s,  o);
        s2 += __shfl_down_sync(0xffffffffu, s2, o);
    }
    __shared__ float sh[8];
    int wr = t >> 5, ln = t & 31;
    if (ln == 0) { sh[wr] = s; sh[wr + 4] = s2; }
    __syncthreads();
    float ts  = sh[0] + sh[1] + sh[2] + sh[3];
    float ts2 = sh[4] + sh[5] + sh[6] + sh[7];
    float mean = ts * (1.0f / CC);
    float var  = ts2 * (1.0f / CC) - mean * mean;
    float rstd = rsqrtf(var + 1e-5f);

    const float4 g4 = *(const float4*)(gamma + t * 4);
    const float4 b4 = *(const float4*)(beta  + t * 4);
    __half2 p0 = __floats2half2_rn((v.x - mean) * rstd * g4.x + b4.x,
                                   (v.y - mean) * rstd * g4.y + b4.y);
    __half2 p1 = __floats2half2_rn((v.z - mean) * rstd * g4.z + b4.z,
                                   (v.w - mean) * rstd * g4.w + b4.w);
    *(__half2*)(out + (size_t)m * CC + t * 4)     = p0;
    *(__half2*)(out + (size_t)m * CC + t * 4 + 2) = p1;
}

// ---------------- fp16 tensor-core GEMM ----------------
// C[m][n] = sum_k A[m][k]*B[n][k]; A(M,K), B(N,K) fp16 row-major.
// CTA tile 256x128, 8 warps (4 m-pos x 2 n-pos), warp tile 64x64.
// K-chunk 64 halves, 3-stage cp.async pipeline, rows padded to 72 halves (144B).

#define ROWB      144
#define A_ST_B    (256 * ROWB)               // 36864
#define B_ST_B    (128 * ROWB)               // 18432
#define STAGE_B   (A_ST_B + B_ST_B)          // 55296
#define NSTG      3
#define HGEMM_SMEM (NSTG * STAGE_B)          // 165888

template <int EPI>
__global__ __launch_bounds__(256, 1)
void hgemm(const __half* __restrict__ A, const __half* __restrict__ B, int K,
           const float* __restrict__ bias, const float* __restrict__ add,
           float* __restrict__ out) {
    extern __shared__ __half sh[];
    const uint32_t sbase = smem_u32(sh);

    const int bn = blockIdx.x, bm = blockIdx.y;
    const int t = threadIdx.x;
    const int lane = t & 31, wid = t >> 5;
    const int wm = wid & 3;          // 4 m positions x 64 rows
    const int wn = wid >> 2;         // 2 n positions x 64 cols
    const int g = lane >> 2, tg = lane & 3;

    const __half* Ag = A + (size_t)(bm * 256) * K;
    const __half* Bg = B + (size_t)(bn * 128) * K;

    float c[4][8][4];
#pragma unroll
    for (int a = 0; a < 4; a++)
#pragma unroll
        for (int b = 0; b < 8; b++)
#pragma unroll
            for (int d = 0; d < 4; d++) c[a][b][d] = 0.0f;

    const int nk = K >> 6;           // K-chunk = 64 halves

    auto load_stage = [&](int cidx) {
        const uint32_t sb = sbase + (uint32_t)(cidx % NSTG) * STAGE_B;
        const __half* Ac = Ag + cidx * 64;
        const __half* Bc = Bg + cidx * 64;
#pragma unroll
        for (int i = 0; i < 8; i++) {          // A: 256 rows x 8 chunks
            int gr = i * 256 + t;
            int row = gr >> 3, q = gr & 7;
            cp16(sb + row * ROWB + q * 16, Ac + (size_t)row * K + q * 8);
        }
#pragma unroll
        for (int i = 0; i < 4; i++) {          // B: 128 rows x 8 chunks
            int gr = i * 256 + t;
            int row = gr >> 3, q = gr & 7;
            cp16(sb + A_ST_B + row * ROWB + q * 16, Bc + (size_t)row * K + q * 8);
        }
        cp_commit();
    };

    load_stage(0);
    if (nk > 1) load_stage(1);

    for (int cc = 0; cc < nk; cc++) {
        if (cc + 2 < nk)      { load_stage(cc + 2); cp_wait<2>(); }
        else if (cc + 1 < nk) { cp_wait<1>(); }
        else                  { cp_wait<0>(); }
        __syncthreads();

        const uint32_t sb = sbase + (uint32_t)(cc % NSTG) * STAGE_B;
        // A: 64 rows at wm*64; fragment rows (lane&15), upper/lower 16B by lane>>4
        const uint32_t aoff = sb + (wm * 64 + (lane & 15)) * ROWB + (lane >> 4) * 16;
        // B x4 over 16 rows: row = p*16 + (lane>>4)*8 + (lane&7), col halves by (lane>>3)&1
        const uint32_t boff = sb + A_ST_B +
                              (wn * 64 + ((lane >> 4) << 3) + (lane & 7)) * ROWB +
                              ((lane >> 3) & 1) * 16;

#pragma unroll
        for (int ks = 0; ks < 4; ks++) {
            const uint32_t kb = ks * 32;       // 16 halves = 32 bytes per k-step
            uint32_t af[4][4], bf[8][2];
#pragma unroll
            for (int mi = 0; mi < 4; mi++)
                ldsm_x4(af[mi], aoff + mi * (16 * ROWB) + kb);
#pragma unroll
            for (int p = 0; p < 4; p++) {
                uint32_t r4[4];
                ldsm_x4(r4, boff + p * (16 * ROWB) + kb);
                bf[2 * p][0] = r4[0]; bf[2 * p][1] = r4[1];
                bf[2 * p + 1][0] = r4[2]; bf[2 * p + 1][1] = r4[3];
            }
#pragma unroll
            for (int mi = 0; mi < 4; mi++)
#pragma unroll
                for (int ni = 0; ni < 8; ni++)
                    mma_f16(c[mi][ni], af[mi], bf[ni]);
        }
        __syncthreads();
    }

    // ---------------- epilogue ----------------
#pragma unroll
    for (int mi = 0; mi < 4; mi++) {
#pragma unroll
        for (int half = 0; half < 2; half++) {
            const int m = bm * 256 + wm * 64 + mi * 16 + g + half * 8;
#pragma unroll
            for (int ni = 0; ni < 8; ni++) {
                const int n = bn * 128 + wn * 64 + ni * 8 + 2 * tg;
                float v0 = c[mi][ni][half * 2 + 0];
                float v1 = c[mi][ni][half * 2 + 1];
                if (EPI == 0) {            // QKV: bias + scatter to fp16 planes
                    __half* oh = (__half*)out;
                    int w = m >> 6, nn = m & 63;
                    int which = n >> 9, r = n & 511;
                    int h = r >> 5, d = r & 31;
                    size_t idx = (size_t)which * PLANE +
                                 ((((size_t)w * NHEAD + h) * NWTOK + nn) << 5) + d;
                    *(__half2*)&oh[idx] = __floats2half2_rn(v0 + bias[n], v1 + bias[n + 1]);
                } else if (EPI == 1) {     // proj: window-reverse + residual (fp32)
                    size_t gi = win_to_nat(m);
                    const float2 a2 = *(const float2*)&add[gi * CC + n];
                    float2 o;
                    o.x = v0 + bias[n] + a2.x;
                    o.y = v1 + bias[n + 1] + a2.y;
                    *(float2*)&out[gi * CC + n] = o;
                } else if (EPI == 2) {     // fc1 + exact GELU -> fp16
                    float z0 = v0 + bias[n];
                    float z1 = v1 + bias[n + 1];
                    float g0 = 0.5f * z0 * (1.0f + erff(z0 * 0.70710678118654752440f));
                    float g1 = 0.5f * z1 * (1.0f + erff(z1 * 0.70710678118654752440f));
                    __half* oh = (__half*)out;
                    *(__half2*)&oh[(size_t)m * HID + n] = __floats2half2_rn(g0, g1);
                } else {                   // fc2 + residual (fp32 final)
                    const float2 a2 = *(const float2*)&add[(size_t)m * CC + n];
                    float2 o;
                    o.x = v0 + bias[n] + a2.x;
                    o.y = v1 + bias[n + 1] + a2.y;
                    *(float2*)&out[(size_t)m * CC + n] = o;
                }
            }
        }
    }
}

// ---------------- tensor-core windowed attention ----------------
#define ATT_ROWH   40
#define ATT_ROWB   80
#define ATT_TILE_B (64 * ATT_ROWB)
#define ATT_WHICH_B (4 * ATT_TILE_B)
#define ATT_CT_OFF  (3 * ATT_WHICH_B)
#define ATT_ST_OFF  (ATT_CT_OFF + 3840)
#define ATT_AR_OFF  (ATT_ST_OFF + 3840)
#define ATT_BR_OFF  (ATT_AR_OFF + 240)
#define ATT_SMEM    69632

__global__ __launch_bounds__(256)
void attn_mma_kernel(const float* __restrict__ D,
                     const float* __restrict__ a_r,
                     const float* __restrict__ b_r,
                     const float* __restrict__ aphi,
                     const __half* __restrict__ qkv,
                     __half* __restrict__ outbuf) {
    extern __shared__ __align__(16) char smraw[];
    const uint32_t sbase = smem_u32(smraw);
    float* ctp = (float*)(smraw + ATT_CT_OFF);
    float* stp = (float*)(smraw + ATT_ST_OFF);
    float* arp = (float*)(smraw + ATT_AR_OFF);
    float* brp = (float*)(smraw + ATT_BR_OFF);

    const int w  = blockIdx.x;
    const int h0 = blockIdx.y * 4;
    const int t  = threadIdx.x;
    const int lane = t & 31, wid = t >> 5;
    const int g = lane >> 2, tg = lane & 3;

#pragma unroll
    for (int i = 0; i < 12; i++) {
        int idx = i * 256 + t;
        int which = idx >> 10;
        int rem = idx & 1023;
        int lh = rem >> 8;
        int row = (rem >> 2) & 63;
        int q = rem & 3;
        const __half* src = qkv + (size_t)which * PLANE +
                            ((((size_t)w * NHEAD + h0 + lh) * NWTOK + row) << 5) + q * 8;
        cp16(sbase + which * ATT_WHICH_B + lh * ATT_TILE_B + row * ATT_ROWB + q * 16, src);
    }
    cp_commit();

    {
        const float KR = 2.0f * PI_F / 256.0f;
        int b = w >> 6, wy = (w >> 3) & 7, wx = w & 7;
        for (int idx = t; idx < 960; idx += 256) {
            int r = idx >> 6, j = idx & 63;
            int ny = j >> 3, nx = j & 7;
            float dj = D[(size_t)b * 4096 + (size_t)(wy * 8 + ny) * 64 + (wx * 8 + nx)];
            float ss, cc;
            __sincosf((float)(r - 7) * dj * KR, &ss, &cc);
            ctp[idx] = cc;
            stp[idx] = ss;
        }
    }
    if (t < 60) {
        int lh = t / 15, r = t % 15;
        arp[t] = a_r[r * NHEAD + h0 + lh];
        brp[t] = b_r[r * NHEAD + h0 + lh];
    }
    cp_wait<0>();
    __syncthreads();

    const int lh = wid >> 1;
    const int h  = h0 + lh;
    const int r0 = (wid & 1) * 32;
    const uint32_t qb = sbase + 0 * ATT_WHICH_B + lh * ATT_TILE_B;
    const uint32_t kb = sbase + 1 * ATT_WHICH_B + lh * ATT_TILE_B;
    const uint32_t vb = sbase + 2 * ATT_WHICH_B + lh * ATT_TILE_B;

    uint32_t qf[2][2][4];
#pragma unroll
    for (int mt = 0; mt < 2; mt++)
#pragma unroll
        for (int kt = 0; kt < 2; kt++)
            ldsm_x4(qf[mt][kt],
                    qb + (r0 + mt * 16 + (lane & 15)) * ATT_ROWB + (lane >> 4) * 16 + kt * 32);

    float sf[2][8][4];
#pragma unroll
    for (int nt = 0; nt < 8; nt++) {
        uint32_t kf[2][2];
#pragma unroll
        for (int kt = 0; kt < 2; kt++)
            ldsm_x2(kf[kt],
                    kb + (nt * 8 + (lane & 7)) * ATT_ROWB + ((lane >> 3) & 1) * 16 + kt * 32);
#pragma unroll
        for (int mt = 0; mt < 2; mt++) {
            sf[mt][nt][0] = sf[mt][nt][1] = sf[mt][nt][2] = sf[mt][nt][3] = 0.0f;
#pragma unroll
            for (int kt = 0; kt < 2; kt++)
                mma_f16(sf[mt][nt], qf[mt][kt], kf[kt]);
        }
    }

    const float scale = 0.1767766952966369f;
    float mx[2][2] = {{-1e30f, -1e30f}, {-1e30f, -1e30f}};
#pragma unroll
    for (int mt = 0; mt < 2; mt++) {
        const int i0 = r0 + mt * 16 + g;
        const int i1 = i0 + 8;
        const int yi0 = i0 >> 3, yi1 = i1 >> 3;
        const float* ap0 = aphi + ((h * 64 + i0) << 6);
        const float* ap1 = aphi + ((h * 64 + i1) << 6);
#pragma unroll
        for (int nt = 0; nt < 8; nt++) {
            const int j0 = nt * 8 + 2 * tg;
            {
                int rad = yi0 - nt;
                int rx = rad + 7;
                int ir = rad < 0 ? rad + 15 : rad;
                float ar = arp[lh * 15 + ir], br = brp[lh * 15 + ir];
                float s0 = sf[mt][nt][0] * scale + ap0[j0]     + ar * ctp[rx * 64 + j0]     + br * stp[rx * 64 + j0];
                float s1 = sf[mt][nt][1] * scale + ap0[j0 + 1] + ar * ctp[rx * 64 + j0 + 1] + br * stp[rx * 64 + j0 + 1];
                sf[mt][nt][0] = s0; sf[mt][nt][1] = s1;
                mx[mt][0] = fmaxf(mx[mt][0], fmaxf(s0, s1));
            }
            {
                int rad = yi1 - nt;
                int rx = rad + 7;
                int ir = rad < 0 ? rad + 15 : rad;
                float ar = arp[lh * 15 + ir], br = brp[lh * 15 + ir];
                float s2 = sf[mt][nt][2] * scale + ap1[j0]     + ar * ctp[rx * 64 + j0]     + br * stp[rx * 64 + j0];
                float s3 = sf[mt][nt][3] * scale + ap1[j0 + 1] + ar * ctp[rx * 64 + j0 + 1] + br * stp[rx * 64 + j0 + 1];
                sf[mt][nt][2] = s2; sf[mt][nt][3] = s3;
                mx[mt][1] = fmaxf(mx[mt][1], fmaxf(s2, s3));
            }
        }
    }
#pragma unroll
    for (int mt = 0; mt < 2; mt++)
#pragma unroll
        for (int hh = 0; hh < 2; hh++) {
            float v = mx[mt][hh];
            v = fmaxf(v, __shfl_xor_sync(0xffffffffu, v, 1));
            v = fmaxf(v, __shfl_xor_sync(0xffffffffu, v, 2));
            mx[mt][hh] = v;
        }

    uint32_t ph[2][8][2];
    float inv[2][2];
#pragma unroll
    for (int mt = 0; mt < 2; mt++) {
        float sum0 = 0.0f, sum1 = 0.0f;
#pragma unroll
        for (int nt = 0; nt < 8; nt++) {
            float e0 = __expf(sf[mt][nt][0] - mx[mt][0]);
            float e1 = __expf(sf[mt][nt][1] - mx[mt][0]);
            float e2 = __expf(sf[mt][nt][2] - mx[mt][1]);
            float e3 = __expf(sf[mt][nt][3] - mx[mt][1]);
            sum0 += e0 + e1;
            sum1 += e2 + e3;
            ph[mt][nt][0] = pack2(e0, e1);
            ph[mt][nt][1] = pack2(e2, e3);
        }
        sum0 += __shfl_xor_sync(0xffffffffu, sum0, 1);
        sum0 += __shfl_xor_sync(0xffffffffu, sum0, 2);
        sum1 += __shfl_xor_sync(0xffffffffu, sum1, 1);
        sum1 += __shfl_xor_sync(0xffffffffu, sum1, 2);
        inv[mt][0] = 1.0f / sum0;
        inv[mt][1] = 1.0f / sum1;
    }

    float of[2][4][4];
#pragma unroll
    for (int mt = 0; mt < 2; mt++)
#pragma unroll
        for (int vn = 0; vn < 4; vn++)
            of[mt][vn][0] = of[mt][vn][1] = of[mt][vn][2] = of[mt][vn][3] = 0.0f;

#pragma unroll
    for (int kt2 = 0; kt2 < 4; kt2++) {
        uint32_t bv[4][2];
#pragma unroll
        for (int vn = 0; vn < 4; vn++)
            ldsm_x2_trans(bv[vn], vb + (kt2 * 16 + (lane & 15)) * ATT_ROWB + vn * 16);
#pragma unroll
        for (int mt = 0; mt < 2; mt++) {
            uint32_t a[4] = {ph[mt][2 * kt2][0], ph[mt][2 * kt2][1],
                             ph[mt][2 * kt2 + 1][0], ph[mt][2 * kt2 + 1][1]};
#pragma unroll
            for (int vn = 0; vn < 4; vn++)
                mma_f16(of[mt][vn], a, bv[vn]);
        }
    }

#pragma unroll
    for (int mt = 0; mt < 2; mt++) {
        const int i0 = r0 + mt * 16 + g;
        const int i1 = i0 + 8;
        __half* o0 = outbuf + ((size_t)(w * 64 + i0)) * CC + h * 32 + 2 * tg;
        __half* o1 = outbuf + ((size_t)(w * 64 + i1)) * CC + h * 32 + 2 * tg;
#pragma unroll
        for (int vn = 0; vn < 4; vn++) {
            *(__half2*)(o0 + vn * 8) = __floats2half2_rn(of[mt][vn][0] * inv[mt][0],
                                                         of[mt][vn][1] * inv[mt][0]);
            *(__half2*)(o1 + vn * 8) = __floats2half2_rn(of[mt][vn][2] * inv[mt][1],
                                                         of[mt][vn][3] * inv[mt][1]);
        }
    }
}

// ---------------- launcher ----------------
extern "C" void kernel_launch(void* const* d_in, const int* in_sizes, int n_in,
                              void* d_out, int out_size) {
    const float* x       = (const float*)d_in[0];
    const float* D       = (const float*)d_in[1];
    const float* norm1_g = (const float*)d_in[2];
    const float* norm1_b = (const float*)d_in[3];
    const float* qkv_w   = (const float*)d_in[4];
    const float* qkv_b   = (const float*)d_in[5];
    const float* proj_w  = (const float*)d_in[6];
    const float* proj_b  = (const float*)d_in[7];
    const float* a_p     = (const float*)d_in[8];
    const float* b_p     = (const float*)d_in[9];
    const float* a_r     = (const float*)d_in[10];
    const float* b_r     = (const float*)d_in[11];
    const float* norm2_g = (const float*)d_in[12];
    const float* norm2_b = (const float*)d_in[13];
    const float* fc1_w   = (const float*)d_in[14];
    const float* fc1_b   = (const float*)d_in[15];
    const float* fc2_w   = (const float*)d_in[16];
    const float* fc2_b   = (const float*)d_in[17];
    float* out = (float*)d_out;

    float *xnw, *qkv, *attno, *x2, *xm, *hbuf, *aphi;
    __half* wh;
    cudaGetSymbolAddress((void**)&xnw,   g_xnw);
    cudaGetSymbolAddress((void**)&qkv,   g_qkv);
    cudaGetSymbolAddress((void**)&attno, g_attnout);
    cudaGetSymbolAddress((void**)&x2,    g_x2);
    cudaGetSymbolAddress((void**)&xm,    g_xm);
    cudaGetSymbolAddress((void**)&hbuf,  g_hbuf);
    cudaGetSymbolAddress((void**)&aphi,  g_aphi);
    cudaGetSymbolAddress((void**)&wh,    g_wh);

    __half* xnw_h   = (__half*)xnw;
    __half* qkv_h   = (__half*)qkv;
    __half* attno_h = (__half*)attno;
    __half* xm_h    = (__half*)xm;
    __half* hbuf_h  = (__half*)hbuf;

    static int smem_set = 0;
    if (!smem_set) {
        cudaFuncSetAttribute(hgemm<0>, cudaFuncAttributeMaxDynamicSharedMemorySize, HGEMM_SMEM);
        cudaFuncSetAttribute(hgemm<1>, cudaFuncAttributeMaxDynamicSharedMemorySize, HGEMM_SMEM);
        cudaFuncSetAttribute(hgemm<2>, cudaFuncAttributeMaxDynamicSharedMemorySize, HGEMM_SMEM);
        cudaFuncSetAttribute(hgemm<3>, cudaFuncAttributeMaxDynamicSharedMemorySize, HGEMM_SMEM);
        cudaFuncSetAttribute(attn_mma_kernel, cudaFuncAttributeMaxDynamicSharedMemorySize, ATT_SMEM);
        smem_set = 1;
    }

    // weight conversions (vectorized x4)
    w2h_kernel<<<768, 256>>>(qkv_w,  wh + WH_QKV,  196608);
    w2h_kernel<<<256, 256>>>(proj_w, wh + WH_PROJ, 65536);
    w2h_kernel<<<1024, 256>>>(fc1_w, wh + WH_FC1,  262144);
    w2h_kernel<<<1024, 256>>>(fc2_w, wh + WH_FC2,  262144);

    aphi_kernel<<<64, 64>>>(a_p, b_p, aphi);
    ln_kernel<1><<<MTOT, 128>>>(x, norm1_g, norm1_b, xnw_h);
    hgemm<0><<<dim3(12, 256), 256, HGEMM_SMEM>>>(xnw_h, wh + WH_QKV, 512, qkv_b, nullptr, (float*)qkv_h);
    attn_mma_kernel<<<dim3(NWIN, 4), 256, ATT_SMEM>>>(D, a_r, b_r, aphi, qkv_h, attno_h);
    hgemm<1><<<dim3(4, 256), 256, HGEMM_SMEM>>>(attno_h, wh + WH_PROJ, 512, proj_b, x, x2);
    ln_kernel<0><<<MTOT, 128>>>(x2, norm2_g, norm2_b, xm_h);
    hgemm<2><<<dim3(16, 256), 256, HGEMM_SMEM>>>(xm_h, wh + WH_FC1, 512, fc1_b, nullptr, (float*)hbuf_h);
    hgemm<3><<<dim3(4, 256), 256, HGEMM_SMEM>>>(hbuf_h, wh + WH_FC2, 2048, fc2_b, x2, out);
}

// round 13
// speedup vs baseline: 1.1247x; 1.1247x over previous
#include <cuda_runtime.h>
#include <cuda_fp16.h>
#include <math.h>
#include <stdint.h>

// ---------------- problem constants ----------------
#define BB      16
#define W_RES   64
#define CC      512
#define NHEAD   16
#define NWTOK   64
#define HD      32
#define HID     2048
#define NWIN    1024
#define MTOT    65536
#define PLANE   33554432ull // MTOT * CC elements per q/k/v plane

#define PI_F    3.14159265358979323846f

// ---------------- scratch ----------------
__device__ float g_xnw[(size_t)MTOT * CC];      // as __half (LN1 out)
__device__ float g_qkv[3ull * MTOT * CC];       // as __half q/k/v planes
__device__ float g_attnout[(size_t)MTOT * CC];  // as __half
__device__ float g_x2[(size_t)MTOT * CC];       // fp32 (residual)
__device__ float g_xm[(size_t)MTOT * CC];       // as __half (LN2 out)
__device__ float g_hbuf[(size_t)MTOT * HID];    // as __half (gelu out)
__device__ __half g_aphi[NHEAD * NWTOK * NWTOK];// fp16 A_phi[h][i][j]
__device__ __half g_wh[3145728];                // fp16 weights: qkv|proj|fc1|fc2

#define WH_QKV  0
#define WH_PROJ 786432
#define WH_FC1  1048576
#define WH_FC2  2097152

__device__ __forceinline__ size_t win_to_nat(int m) {
    int w = m >> 6, n = m & 63;
    int b = w >> 6, wy = (w >> 3) & 7, wx = w & 7;
    int ny = n >> 3, nx = n & 7;
    return (size_t)b * 4096 + (size_t)(wy * 8 + ny) * 64 + (wx * 8 + nx);
}

// ---------------- PTX helpers ----------------
__device__ __forceinline__ uint32_t smem_u32(const void* p) {
    uint32_t a;
    asm("{ .reg .u64 tmp; cvta.to.shared.u64 tmp, %1; cvt.u32.u64 %0, tmp; }"
        : "=r"(a) : "l"(p));
    return a;
}
__device__ __forceinline__ void cp16(uint32_t smem, const void* g) {
    asm volatile("cp.async.cg.shared.global [%0], [%1], 16;\n" :: "r"(smem), "l"(g));
}
__device__ __forceinline__ void cp_commit() {
    asm volatile("cp.async.commit_group;\n" ::: "memory");
}
template <int N>
__device__ __forceinline__ void cp_wait() {
    asm volatile("cp.async.wait_group %0;\n" :: "n"(N) : "memory");
}
__device__ __forceinline__ void ldsm_x4(uint32_t* r, uint32_t addr) {
    asm volatile("ldmatrix.sync.aligned.m8n8.x4.shared.b16 {%0,%1,%2,%3}, [%4];"
                 : "=r"(r[0]), "=r"(r[1]), "=r"(r[2]), "=r"(r[3]) : "r"(addr));
}
__device__ __forceinline__ void ldsm_x2(uint32_t* r, uint32_t addr) {
    asm volatile("ldmatrix.sync.aligned.m8n8.x2.shared.b16 {%0,%1}, [%2];"
                 : "=r"(r[0]), "=r"(r[1]) : "r"(addr));
}
__device__ __forceinline__ void ldsm_x2_trans(uint32_t* r, uint32_t addr) {
    asm volatile("ldmatrix.sync.aligned.m8n8.x2.trans.shared.b16 {%0,%1}, [%2];"
                 : "=r"(r[0]), "=r"(r[1]) : "r"(addr));
}
__device__ __forceinline__ void mma_f16(float* c, const uint32_t* a, const uint32_t* b) {
    asm volatile(
        "mma.sync.aligned.m16n8k16.row.col.f32.f16.f16.f32 "
        "{%0,%1,%2,%3}, {%4,%5,%6,%7}, {%8,%9}, {%0,%1,%2,%3};\n"
        : "+f"(c[0]), "+f"(c[1]), "+f"(c[2]), "+f"(c[3])
        : "r"(a[0]), "r"(a[1]), "r"(a[2]), "r"(a[3]), "r"(b[0]), "r"(b[1]));
}
__device__ __forceinline__ uint32_t pack2(float a, float b) {
    __half2 h = __floats2half2_rn(a, b);
    return *reinterpret_cast<uint32_t*>(&h);
}

// ---------------- all weights fp32 -> fp16, one launch ----------------
__global__ void w2h_all(const float* __restrict__ qkv_w, const float* __restrict__ proj_w,
                        const float* __restrict__ fc1_w, const float* __restrict__ fc2_w,
                        __half* __restrict__ o) {
    int i = blockIdx.x * blockDim.x + threadIdx.x;   // over 786432 float4 groups
    const float* src;
    int off;
    __half* dst;
    if (i < 196608)      { src = qkv_w;  off = i;          dst = o + WH_QKV; }
    else if (i < 262144) { src = proj_w; off = i - 196608; dst = o + WH_PROJ; }
    else if (i < 524288) { src = fc1_w;  off = i - 262144; dst = o + WH_FC1; }
    else                 { src = fc2_w;  off = i - 524288; dst = o + WH_FC2; }
    float4 v = ((const float4*)src)[off];
    __half2 a = __floats2half2_rn(v.x, v.y);
    __half2 b = __floats2half2_rn(v.z, v.w);
    ((uint2*)dst)[off] = make_uint2(*(uint32_t*)&a, *(uint32_t*)&b);
}

// ---------------- A_phi precompute (fp16) ----------------
__global__ void aphi_kernel(const float* __restrict__ a_p,
                            const float* __restrict__ b_p,
                            __half* __restrict__ aphi) {
    int i = blockIdx.x, j = threadIdx.x;
    int az = (i & 7) - (j & 7);
    int ip = (az + 15) % 15;
    float azf = (float)az * (2.0f * PI_F / (float)W_RES);
    float c = cosf(azf), s = sinf(azf);
#pragma unroll
    for (int h = 0; h < NHEAD; h++)
        aphi[((h * 64 + i) << 6) + j] =
            __float2half_rn(a_p[ip * NHEAD + h] * c + b_p[ip * NHEAD + h] * s);
}

// ---------------- LayerNorm (fp32 in, fp16 out) ----------------
template <int WINDOWED>
__global__ __launch_bounds__(128) void ln_kernel(const float* __restrict__ x,
                                                 const float* __restrict__ gamma,
                                                 const float* __restrict__ beta,
                                                 __half* __restrict__ out) {
    int m = blockIdx.x;
    size_t src = WINDOWED ? win_to_nat(m) : (size_t)m;
    int t = threadIdx.x;

    const float4 v = *(const float4*)(x + src * CC + t * 4);
    float s  = v.x + v.y + v.z + v.w;
    float s2 = v.x * v.x + v.y * v.y + v.z * v.z + v.w * v.w;
#pragma unroll
    for (int o = 16; o > 0; o >>= 1) {
        s  += __shfl_down_sync(0xffffffffu, s,  o);
        s2 += __shfl_down_sync(0xffffffffu, s2, o);
    }
    __shared__ float sh[8];
    int wr = t >> 5, ln = t & 31;
    if (ln == 0) { sh[wr] = s; sh[wr + 4] = s2; }
    __syncthreads();
    float ts  = sh[0] + sh[1] + sh[2] + sh[3];
    float ts2 = sh[4] + sh[5] + sh[6] + sh[7];
    float mean = ts * (1.0f / CC);
    float var  = ts2 * (1.0f / CC) - mean * mean;
    float rstd = rsqrtf(var + 1e-5f);

    const float4 g4 = *(const float4*)(gamma + t * 4);
    const float4 b4 = *(const float4*)(beta  + t * 4);
    __half2 p0 = __floats2half2_rn((v.x - mean) * rstd * g4.x + b4.x,
                                   (v.y - mean) * rstd * g4.y + b4.y);
    __half2 p1 = __floats2half2_rn((v.z - mean) * rstd * g4.z + b4.z,
                                   (v.w - mean) * rstd * g4.w + b4.w);
    *(__half2*)(out + (size_t)m * CC + t * 4)     = p0;
    *(__half2*)(out + (size_t)m * CC + t * 4 + 2) = p1;
}

// ---------------- fp16 tensor-core GEMM (128x128, 3-stage, single sync) ----
#define ROWB      144
#define A_ST_B    (128 * ROWB)               // 18432
#define STAGE_B   (2 * A_ST_B)               // 36864 (A+B)
#define NSTG      3
#define HGEMM_SMEM (NSTG * STAGE_B)          // 110592

template <int EPI>
__global__ __launch_bounds__(256, 2)
void hgemm(const __half* __restrict__ A, const __half* __restrict__ B, int K,
           const float* __restrict__ bias, const float* __restrict__ add,
           float* __restrict__ out) {
    extern __shared__ __half sh[];
    const uint32_t sbase = smem_u32(sh);

    const int bn = blockIdx.x, bm = blockIdx.y;
    const int t = threadIdx.x;
    const int lane = t & 31, wid = t >> 5;
    const int wm = wid >> 2, wn = wid & 3;
    const int g = lane >> 2, tg = lane & 3;

    const __half* Ag = A + (size_t)(bm * 128) * K;
    const __half* Bg = B + (size_t)(bn * 128) * K;

    float c[4][4][4];
#pragma unroll
    for (int a = 0; a < 4; a++)
#pragma unroll
        for (int b = 0; b < 4; b++)
#pragma unroll
            for (int d = 0; d < 4; d++) c[a][b][d] = 0.0f;

    const int nk = K >> 6;

    auto load_stage = [&](int cidx) {
        const uint32_t sb = sbase + (uint32_t)(cidx % NSTG) * STAGE_B;
        const __half* Ac = Ag + cidx * 64;
        const __half* Bc = Bg + cidx * 64;
#pragma unroll
        for (int i = 0; i < 4; i++) {
            int gr = i * 256 + t;
            int row = gr >> 3, q = gr & 7;
            cp16(sb + row * ROWB + q * 16, Ac + (size_t)row * K + q * 8);
        }
#pragma unroll
        for (int i = 0; i < 4; i++) {
            int gr = i * 256 + t;
            int row = gr >> 3, q = gr & 7;
            cp16(sb + A_ST_B + row * ROWB + q * 16, Bc + (size_t)row * K + q * 8);
        }
        cp_commit();
    };

    load_stage(0);
    if (nk > 1) load_stage(1);

    for (int cc = 0; cc < nk; cc++) {
        if (cc + 1 < nk) cp_wait<1>(); else cp_wait<0>();
        __syncthreads();
        // safe: stage (cc+2)%3 was last read in iter cc-1, already past this sync
        if (cc + 2 < nk) load_stage(cc + 2);

        const uint32_t sb = sbase + (uint32_t)(cc % NSTG) * STAGE_B;
        const uint32_t aoff = sb + (wm * 64 + (lane & 15)) * ROWB + (lane >> 4) * 16;
        const uint32_t boff = sb + A_ST_B + (wn * 32 + (lane & 7)) * ROWB + ((lane >> 3) & 1) * 16;

#pragma unroll
        for (int ks = 0; ks < 4; ks++) {
            const uint32_t kb = ks * 32;
            uint32_t af[4][4], bf[4][2];
#pragma unroll
            for (int mi = 0; mi < 4; mi++) ldsm_x4(af[mi], aoff + mi * (16 * ROWB) + kb);
#pragma unroll
            for (int ni = 0; ni < 4; ni++) ldsm_x2(bf[ni], boff + ni * (8 * ROWB) + kb);
#pragma unroll
            for (int mi = 0; mi < 4; mi++)
#pragma unroll
                for (int ni = 0; ni < 4; ni++)
                    mma_f16(c[mi][ni], af[mi], bf[ni]);
        }
    }

#pragma unroll
    for (int mi = 0; mi < 4; mi++) {
#pragma unroll
        for (int half = 0; half < 2; half++) {
            const int m = bm * 128 + wm * 64 + mi * 16 + g + half * 8;
#pragma unroll
            for (int ni = 0; ni < 4; ni++) {
                const int n = bn * 128 + wn * 32 + ni * 8 + 2 * tg;
                float v0 = c[mi][ni][half * 2 + 0];
                float v1 = c[mi][ni][half * 2 + 1];
                if (EPI == 0) {            // QKV: bias + scatter to fp16 planes
                    __half* oh = (__half*)out;
                    int w = m >> 6, nn = m & 63;
                    int which = n >> 9, r = n & 511;
                    int h = r >> 5, d = r & 31;
                    size_t idx = (size_t)which * PLANE +
                                 ((((size_t)w * NHEAD + h) * NWTOK + nn) << 5) + d;
                    *(__half2*)&oh[idx] = __floats2half2_rn(v0 + bias[n], v1 + bias[n + 1]);
                } else if (EPI == 1) {     // proj: window-reverse + residual (fp32)
                    size_t gi = win_to_nat(m);
                    const float2 a2 = *(const float2*)&add[gi * CC + n];
                    float2 o;
                    o.x = v0 + bias[n] + a2.x;
                    o.y = v1 + bias[n + 1] + a2.y;
                    *(float2*)&out[gi * CC + n] = o;
                } else if (EPI == 2) {     // fc1 + exact GELU -> fp16
                    float z0 = v0 + bias[n];
                    float z1 = v1 + bias[n + 1];
                    float g0 = 0.5f * z0 * (1.0f + erff(z0 * 0.70710678118654752440f));
                    float g1 = 0.5f * z1 * (1.0f + erff(z1 * 0.70710678118654752440f));
                    __half* oh = (__half*)out;
                    *(__half2*)&oh[(size_t)m * HID + n] = __floats2half2_rn(g0, g1);
                } else {                   // fc2 + residual (fp32 final)
                    const float2 a2 = *(const float2*)&add[(size_t)m * CC + n];
                    float2 o;
                    o.x = v0 + bias[n] + a2.x;
                    o.y = v1 + bias[n + 1] + a2.y;
                    *(float2*)&out[(size_t)m * CC + n] = o;
                }
            }
        }
    }
}

// ---------------- tensor-core windowed attention ----------------
// smem: Q/K/V fp16 tiles [which][head][64][40] + combined fp16 bias table
// biasr[lh][rx][j] = a_r*cos + b_r*sin, + arp/brp staging.
#define ATT_ROWB    80
#define ATT_TILE_B  (64 * ATT_ROWB)          // 5120
#define ATT_WHICH_B (4 * ATT_TILE_B)         // 20480
#define ATT_BIAS_OFF (3 * ATT_WHICH_B)       // 61440 (4*960 halves = 7680 B)
#define ATT_AR_OFF  (ATT_BIAS_OFF + 7680)    // 69120 (60 floats)
#define ATT_BR_OFF  (ATT_AR_OFF + 240)       // 69360 (60 floats)
#define ATT_SMEM    69632

__global__ __launch_bounds__(256)
void attn_mma_kernel(const float* __restrict__ D,
                     const float* __restrict__ a_r,
                     const float* __restrict__ b_r,
                     const __half* __restrict__ aphi,
                     const __half* __restrict__ qkv,
                     __half* __restrict__ outbuf) {
    extern __shared__ __align__(16) char smraw[];
    const uint32_t sbase = smem_u32(smraw);
    __half* biasr = (__half*)(smraw + ATT_BIAS_OFF);
    float* arp = (float*)(smraw + ATT_AR_OFF);
    float* brp = (float*)(smraw + ATT_BR_OFF);

    const int w  = blockIdx.x;
    const int h0 = blockIdx.y * 4;
    const int t  = threadIdx.x;
    const int lane = t & 31, wid = t >> 5;
    const int g = lane >> 2, tg = lane & 3;

    // ---- async load Q/K/V tiles for 4 heads ----
#pragma unroll
    for (int i = 0; i < 12; i++) {
        int idx = i * 256 + t;
        int which = idx >> 10;
        int rem = idx & 1023;
        int lh = rem >> 8;
        int row = (rem >> 2) & 63;
        int q = rem & 3;
        const __half* src = qkv + (size_t)which * PLANE +
                            ((((size_t)w * NHEAD + h0 + lh) * NWTOK + row) << 5) + q * 8;
        cp16(sbase + which * ATT_WHICH_B + lh * ATT_TILE_B + row * ATT_ROWB + q * 16, src);
    }
    cp_commit();

    // ---- a_r/b_r gather for 4 heads ----
    if (t < 60) {
        int lh = t / 15, r = t % 15;
        arp[t] = a_r[r * NHEAD + h0 + lh];
        brp[t] = b_r[r * NHEAD + h0 + lh];
    }
    __syncthreads();

    // ---- combined bias table: one thread per key j ----
    if (t < 64) {
        const float KR = 2.0f * PI_F / 256.0f;
        int b = w >> 6, wy = (w >> 3) & 7, wx = w & 7;
        int ny = t >> 3, nx = t & 7;
        float dj = D[(size_t)b * 4096 + (size_t)(wy * 8 + ny) * 64 + (wx * 8 + nx)];
#pragma unroll
        for (int rx = 0; rx < 15; rx++) {
            int rad = rx - 7;
            int ir = rad < 0 ? rad + 15 : rad;
            float ss, cc;
            __sincosf((float)rad * dj * KR, &ss, &cc);
#pragma unroll
            for (int lh = 0; lh < 4; lh++)
                biasr[lh * 960 + rx * 64 + t] =
                    __float2half_rn(arp[lh * 15 + ir] * cc + brp[lh * 15 + ir] * ss);
        }
    }
    cp_wait<0>();
    __syncthreads();

    const int lh = wid >> 1;
    const int h  = h0 + lh;
    const int r0 = (wid & 1) * 32;
    const uint32_t qb = sbase + 0 * ATT_WHICH_B + lh * ATT_TILE_B;
    const uint32_t kb = sbase + 1 * ATT_WHICH_B + lh * ATT_TILE_B;
    const uint32_t vb = sbase + 2 * ATT_WHICH_B + lh * ATT_TILE_B;
    const __half* bias_h = biasr + lh * 960;

    uint32_t qf[2][2][4];
#pragma unroll
    for (int mt = 0; mt < 2; mt++)
#pragma unroll
        for (int kt = 0; kt < 2; kt++)
            ldsm_x4(qf[mt][kt],
                    qb + (r0 + mt * 16 + (lane & 15)) * ATT_ROWB + (lane >> 4) * 16 + kt * 32);

    float sf[2][8][4];
#pragma unroll
    for (int nt = 0; nt < 8; nt++) {
        uint32_t kf[2][2];
#pragma unroll
        for (int kt = 0; kt < 2; kt++)
            ldsm_x2(kf[kt],
                    kb + (nt * 8 + (lane & 7)) * ATT_ROWB + ((lane >> 3) & 1) * 16 + kt * 32);
#pragma unroll
        for (int mt = 0; mt < 2; mt++) {
            sf[mt][nt][0] = sf[mt][nt][1] = sf[mt][nt][2] = sf[mt][nt][3] = 0.0f;
#pragma unroll
            for (int kt = 0; kt < 2; kt++)
                mma_f16(sf[mt][nt], qf[mt][kt], kf[kt]);
        }
    }

    // ---- bias + scale + row max ----
    const float scale = 0.1767766952966369f;
    float mx[2][2] = {{-1e30f, -1e30f}, {-1e30f, -1e30f}};
#pragma unroll
    for (int mt = 0; mt < 2; mt++) {
        const int i0 = r0 + mt * 16 + g;
        const int i1 = i0 + 8;
        const int yi0 = i0 >> 3, yi1 = i1 >> 3;
        const __half* ap0 = aphi + ((h * 64 + i0) << 6);
        const __half* ap1 = aphi + ((h * 64 + i1) << 6);
#pragma unroll
        for (int nt = 0; nt < 8; nt++) {
            const int j0 = nt * 8 + 2 * tg;
            {
                int rx = yi0 - nt + 7;
                float2 bb = __half22float2(*(const __half2*)&bias_h[rx * 64 + j0]);
                float2 aa = __half22float2(*(const __half2*)&ap0[j0]);
                float s0 = sf[mt][nt][0] * scale + aa.x + bb.x;
                float s1 = sf[mt][nt][1] * scale + aa.y + bb.y;
                sf[mt][nt][0] = s0; sf[mt][nt][1] = s1;
                mx[mt][0] = fmaxf(mx[mt][0], fmaxf(s0, s1));
            }
            {
                int rx = yi1 - nt + 7;
                float2 bb = __half22float2(*(const __half2*)&bias_h[rx * 64 + j0]);
                float2 aa = __half22float2(*(const __half2*)&ap1[j0]);
                float s2 = sf[mt][nt][2] * scale + aa.x + bb.x;
                float s3 = sf[mt][nt][3] * scale + aa.y + bb.y;
                sf[mt][nt][2] = s2; sf[mt][nt][3] = s3;
                mx[mt][1] = fmaxf(mx[mt][1], fmaxf(s2, s3));
            }
        }
    }
#pragma unroll
    for (int mt = 0; mt < 2; mt++)
#pragma unroll
        for (int hh = 0; hh < 2; hh++) {
            float v = mx[mt][hh];
            v = fmaxf(v, __shfl_xor_sync(0xffffffffu, v, 1));
            v = fmaxf(v, __shfl_xor_sync(0xffffffffu, v, 2));
            mx[mt][hh] = v;
        }

    uint32_t ph[2][8][2];
    float inv[2][2];
#pragma unroll
    for (int mt = 0; mt < 2; mt++) {
        float sum0 = 0.0f, sum1 = 0.0f;
#pragma unroll
        for (int nt = 0; nt < 8; nt++) {
            float e0 = __expf(sf[mt][nt][0] - mx[mt][0]);
            float e1 = __expf(sf[mt][nt][1] - mx[mt][0]);
            float e2 = __expf(sf[mt][nt][2] - mx[mt][1]);
            float e3 = __expf(sf[mt][nt][3] - mx[mt][1]);
            sum0 += e0 + e1;
            sum1 += e2 + e3;
            ph[mt][nt][0] = pack2(e0, e1);
            ph[mt][nt][1] = pack2(e2, e3);
        }
        sum0 += __shfl_xor_sync(0xffffffffu, sum0, 1);
        sum0 += __shfl_xor_sync(0xffffffffu, sum0, 2);
        sum1 += __shfl_xor_sync(0xffffffffu, sum1, 1);
        sum1 += __shfl_xor_sync(0xffffffffu, sum1, 2);
        inv[mt][0] = 1.0f / sum0;
        inv[mt][1] = 1.0f / sum1;
    }

    float of[2][4][4];
#pragma unroll
    for (int mt = 0; mt < 2; mt++)
#pragma unroll
        for (int vn = 0; vn < 4; vn++)
            of[mt][vn][0] = of[mt][vn][1] = of[mt][vn][2] = of[mt][vn][3] = 0.0f;

#pragma unroll
    for (int kt2 = 0; kt2 < 4; kt2++) {
        uint32_t bv[4][2];
#pragma unroll
        for (int vn = 0; vn < 4; vn++)
            ldsm_x2_trans(bv[vn], vb + (kt2 * 16 + (lane & 15)) * ATT_ROWB + vn * 16);
#pragma unroll
        for (int mt = 0; mt < 2; mt++) {
            uint32_t a[4] = {ph[mt][2 * kt2][0], ph[mt][2 * kt2][1],
                             ph[mt][2 * kt2 + 1][0], ph[mt][2 * kt2 + 1][1]};
#pragma unroll
            for (int vn = 0; vn < 4; vn++)
                mma_f16(of[mt][vn], a, bv[vn]);
        }
    }

#pragma unroll
    for (int mt = 0; mt < 2; mt++) {
        const int i0 = r0 + mt * 16 + g;
        const int i1 = i0 + 8;
        __half* o0 = outbuf + ((size_t)(w * 64 + i0)) * CC + h * 32 + 2 * tg;
        __half* o1 = outbuf + ((size_t)(w * 64 + i1)) * CC + h * 32 + 2 * tg;
#pragma unroll
        for (int vn = 0; vn < 4; vn++) {
            *(__half2*)(o0 + vn * 8) = __floats2half2_rn(of[mt][vn][0] * inv[mt][0],
                                                         of[mt][vn][1] * inv[mt][0]);
            *(__half2*)(o1 + vn * 8) = __floats2half2_rn(of[mt][vn][2] * inv[mt][1],
                                                         of[mt][vn][3] * inv[mt][1]);
        }
    }
}

// ---------------- launcher ----------------
extern "C" void kernel_launch(void* const* d_in, const int* in_sizes, int n_in,
                              void* d_out, int out_size) {
    const float* x       = (const float*)d_in[0];
    const float* D       = (const float*)d_in[1];
    const float* norm1_g = (const float*)d_in[2];
    const float* norm1_b = (const float*)d_in[3];
    const float* qkv_w   = (const float*)d_in[4];
    const float* qkv_b   = (const float*)d_in[5];
    const float* proj_w  = (const float*)d_in[6];
    const float* proj_b  = (const float*)d_in[7];
    const float* a_p     = (const float*)d_in[8];
    const float* b_p     = (const float*)d_in[9];
    const float* a_r     = (const float*)d_in[10];
    const float* b_r     = (const float*)d_in[11];
    const float* norm2_g = (const float*)d_in[12];
    const float* norm2_b = (const float*)d_in[13];
    const float* fc1_w   = (const float*)d_in[14];
    const float* fc1_b   = (const float*)d_in[15];
    const float* fc2_w   = (const float*)d_in[16];
    const float* fc2_b   = (const float*)d_in[17];
    float* out = (float*)d_out;

    float *xnw, *qkv, *attno, *x2, *xm, *hbuf;
    __half *wh, *aphi;
    cudaGetSymbolAddress((void**)&xnw,   g_xnw);
    cudaGetSymbolAddress((void**)&qkv,   g_qkv);
    cudaGetSymbolAddress((void**)&attno, g_attnout);
    cudaGetSymbolAddress((void**)&x2,    g_x2);
    cudaGetSymbolAddress((void**)&xm,    g_xm);
    cudaGetSymbolAddress((void**)&hbuf,  g_hbuf);
    cudaGetSymbolAddress((void**)&aphi,  g_aphi);
    cudaGetSymbolAddress((void**)&wh,    g_wh);

    __half* xnw_h   = (__half*)xnw;
    __half* qkv_h   = (__half*)qkv;
    __half* attno_h = (__half*)attno;
    __half* xm_h    = (__half*)xm;
    __half* hbuf_h  = (__half*)hbuf;

    static int smem_set = 0;
    if (!smem_set) {
        cudaFuncSetAttribute(hgemm<0>, cudaFuncAttributeMaxDynamicSharedMemorySize, HGEMM_SMEM);
        cudaFuncSetAttribute(hgemm<1>, cudaFuncAttributeMaxDynamicSharedMemorySize, HGEMM_SMEM);
        cudaFuncSetAttribute(hgemm<2>, cudaFuncAttributeMaxDynamicSharedMemorySize, HGEMM_SMEM);
        cudaFuncSetAttribute(hgemm<3>, cudaFuncAttributeMaxDynamicSharedMemorySize, HGEMM_SMEM);
        cudaFuncSetAttribute(attn_mma_kernel, cudaFuncAttributeMaxDynamicSharedMemorySize, ATT_SMEM);
        smem_set = 1;
    }

    w2h_all<<<3072, 256>>>(qkv_w, proj_w, fc1_w, fc2_w, wh);
    aphi_kernel<<<64, 64>>>(a_p, b_p, aphi);
    ln_kernel<1><<<MTOT, 128>>>(x, norm1_g, norm1_b, xnw_h);
    hgemm<0><<<dim3(12, 512), 256, HGEMM_SMEM>>>(xnw_h, wh + WH_QKV, 512, qkv_b, nullptr, (float*)qkv_h);
    attn_mma_kernel<<<dim3(NWIN, 4), 256, ATT_SMEM>>>(D, a_r, b_r, aphi, qkv_h, attno_h);
    hgemm<1><<<dim3(4, 512), 256, HGEMM_SMEM>>>(attno_h, wh + WH_PROJ, 512, proj_b, x, x2);
    ln_kernel<0><<<MTOT, 128>>>(x2, norm2_g, norm2_b, xm_h);
    hgemm<2><<<dim3(16, 512), 256, HGEMM_SMEM>>>(xm_h, wh + WH_FC1, 512, fc1_b, nullptr, (float*)hbuf_h);
    hgemm<3><<<dim3(4, 512), 256, HGEMM_SMEM>>>(hbuf_h, wh + WH_FC2, 2048, fc2_b, x2, out);
}